// round 6
// baseline (speedup 1.0000x reference)
#include <cuda_runtime.h>
#include <cuda_bf16.h>
#include <cstdint>

#define MAXN 100000
#define MAXE 1600000

// ---------------- device scratch ----------------
__device__ int   g_is64;
__device__ int   g_deg[MAXN];
__device__ int   g_off[MAXN + 1];
__device__ int   g_cur[MAXN];
__device__ int   g_bsum[128];
__device__ int   g_bucket[MAXE];
__device__ float g_h[(size_t)MAXN * 256];    // hidden activations
__device__ float g_tu[(size_t)MAXN * 128];   // layer2: [t(64) | u(64)]

// ---------------- edge dtype detection ----------------
__global__ void detect_kernel(const int* __restrict__ w) {
    __shared__ int any;
    if (threadIdx.x == 0) any = 0;
    __syncthreads();
    if (w[2 * threadIdx.x + 1] != 0) atomicOr(&any, 1);
    __syncthreads();
    if (threadIdx.x == 0) g_is64 = (any == 0) ? 1 : 0;
}

__device__ __forceinline__ int load_idx(const void* ei, int pos) {
    if (g_is64) return (int)((const long long*)ei)[pos];
    return ((const int*)ei)[pos];
}

// ---------------- CSR construction ----------------
__global__ void zero_deg_kernel(int N) {
    int i = blockIdx.x * blockDim.x + threadIdx.x;
    if (i < N) g_deg[i] = 0;
}

__global__ void count_kernel(const void* __restrict__ ei, int E, int N) {
    int e = blockIdx.x * blockDim.x + threadIdx.x;
    if (e < E) {
        int d = load_idx(ei, E + e);
        if ((unsigned)d < (unsigned)N) atomicAdd(&g_deg[d], 1);
    }
}

__global__ void scan_blocks(int N) {
    __shared__ int wsum[32];
    int i = blockIdx.x * 1024 + threadIdx.x;
    int lane = threadIdx.x & 31, wid = threadIdx.x >> 5;
    int v = (i < N) ? g_deg[i] : 0;
    int s = v;
    #pragma unroll
    for (int o = 1; o < 32; o <<= 1) {
        int t = __shfl_up_sync(0xffffffffu, s, o);
        if (lane >= o) s += t;
    }
    if (lane == 31) wsum[wid] = s;
    __syncthreads();
    if (wid == 0) {
        int ws = wsum[lane];
        #pragma unroll
        for (int o = 1; o < 32; o <<= 1) {
            int t = __shfl_up_sync(0xffffffffu, ws, o);
            if (lane >= o) ws += t;
        }
        wsum[lane] = ws;
    }
    __syncthreads();
    int incl = s + (wid > 0 ? wsum[wid - 1] : 0);
    if (i < N) g_off[i] = incl - v;
    if (threadIdx.x == 1023) g_bsum[blockIdx.x] = incl;
}

__global__ void scan_bsums(int B) {
    int lane = threadIdx.x;
    int carry = 0;
    for (int base = 0; base < B; base += 32) {
        int i = base + lane;
        int v = (i < B) ? g_bsum[i] : 0;
        int s = v;
        #pragma unroll
        for (int o = 1; o < 32; o <<= 1) {
            int t = __shfl_up_sync(0xffffffffu, s, o);
            if (lane >= o) s += t;
        }
        if (i < B) g_bsum[i] = carry + s - v;
        carry += __shfl_sync(0xffffffffu, s, 31);
    }
}

__global__ void finalize_off(int N, int E) {
    int i = blockIdx.x * blockDim.x + threadIdx.x;
    if (i < N) {
        int o = g_off[i] + g_bsum[i >> 10];
        g_off[i] = o;
        g_cur[i] = o;
    }
    if (i == 0) g_off[N] = E;
}

__global__ void fill_kernel(const void* __restrict__ ei, int E, int N) {
    int e = blockIdx.x * blockDim.x + threadIdx.x;
    if (e < E) {
        int s = load_idx(ei, e);
        int d = load_idx(ei, E + e);
        if ((unsigned)d < (unsigned)N && (unsigned)s < (unsigned)N) {
            int pos = atomicAdd(&g_cur[d], 1);
            g_bucket[pos] = s;
        }
    }
}

__device__ __forceinline__ unsigned f2tf32(float v) {
    unsigned r;
    asm("cvt.rna.tf32.f32 %0, %1;" : "=r"(r) : "f"(v));
    return r;
}

// ---------------- fused layer 1: gather-mean + TF32 GEMM + bias + relu ----------------
// Block = 128 nodes x 256 output cols. 256 threads = 8 warps (2m x 4n), warp tile 64x64.
// Phase 1: mean-agg of x for the block's 128 nodes -> agg_s (tf32, smem).
// Phase 2: g_h = relu( [agg_s | x] (K=256) @ [W1l ; W1r] + b1 ).
#define L1_SMEM_WORDS (128 * 132 + 128 * 36 + 32 * 264)

__global__ void __launch_bounds__(256, 1)
fused_l1(const float* __restrict__ x,
         const float* __restrict__ W1l, const float* __restrict__ W1r,
         const float* __restrict__ bias, int M) {
    extern __shared__ unsigned smem_u[];
    unsigned (*agg_s)[132] = (unsigned(*)[132])smem_u;                         // 128x132
    unsigned (*As)[36]     = (unsigned(*)[36])(smem_u + 128 * 132);            // 128x36
    unsigned (*Ws)[264]    = (unsigned(*)[264])(smem_u + 128 * 132 + 128 * 36);// 32x264

    int tid = threadIdx.x;
    int lane = tid & 31;
    int wid = tid >> 5;
    int row0 = blockIdx.y * 128;

    // ---- Phase 1: gather-mean, warp w handles nodes w*16 .. w*16+15 ----
    for (int i = 0; i < 16; i++) {
        int nloc = wid * 16 + i;
        int node = row0 + nloc;
        float4 acc = make_float4(0.f, 0.f, 0.f, 0.f);
        if (node < M) {
            int beg = g_off[node], end = g_off[node + 1];
            int e = beg;
            for (; e + 4 <= end; e += 4) {
                int s0 = g_bucket[e], s1 = g_bucket[e + 1], s2 = g_bucket[e + 2], s3 = g_bucket[e + 3];
                float4 v0 = *(const float4*)&x[(size_t)s0 * 128 + lane * 4];
                float4 v1 = *(const float4*)&x[(size_t)s1 * 128 + lane * 4];
                float4 v2 = *(const float4*)&x[(size_t)s2 * 128 + lane * 4];
                float4 v3 = *(const float4*)&x[(size_t)s3 * 128 + lane * 4];
                acc.x += v0.x + v1.x + v2.x + v3.x;
                acc.y += v0.y + v1.y + v2.y + v3.y;
                acc.z += v0.z + v1.z + v2.z + v3.z;
                acc.w += v0.w + v1.w + v2.w + v3.w;
            }
            for (; e < end; ++e) {
                int s = g_bucket[e];
                float4 v = *(const float4*)&x[(size_t)s * 128 + lane * 4];
                acc.x += v.x; acc.y += v.y; acc.z += v.z; acc.w += v.w;
            }
            float inv = (end > beg) ? 1.f / (float)(end - beg) : 0.f;
            acc.x *= inv; acc.y *= inv; acc.z *= inv; acc.w *= inv;
        }
        uint4 t;
        t.x = f2tf32(acc.x); t.y = f2tf32(acc.y);
        t.z = f2tf32(acc.z); t.w = f2tf32(acc.w);
        *(uint4*)&agg_s[nloc][lane * 4] = t;
    }
    __syncthreads();

    // ---- Phase 2: GEMM ----
    int warp_m = wid & 1;        // 64 rows each
    int warp_n = wid >> 1;       // 64 cols each
    int qk = lane & 3;
    int qr = lane >> 2;

    float d[4][8][4];
    #pragma unroll
    for (int i = 0; i < 4; i++)
        #pragma unroll
        for (int j = 0; j < 8; j++)
            #pragma unroll
            for (int q = 0; q < 4; q++) d[i][j][q] = 0.f;

    for (int k0 = 0; k0 < 256; k0 += 32) {
        bool xhalf = (k0 >= 128);
        // A tile from x (only for k0>=128); agg half read directly from agg_s
        if (xhalf) {
            #pragma unroll
            for (int it = 0; it < 4; it++) {
                int f = tid + it * 256;
                int m = f >> 3;
                int k = (f & 7) * 4;
                int grow = row0 + m;
                float4 v = make_float4(0, 0, 0, 0);
                if (grow < M) v = *(const float4*)&x[(size_t)grow * 128 + (k0 - 128) + k];
                As[m][k + 0] = f2tf32(v.x); As[m][k + 1] = f2tf32(v.y);
                As[m][k + 2] = f2tf32(v.z); As[m][k + 3] = f2tf32(v.w);
            }
        }
        // W tile: 32 k x 256 n
        {
            const float* Wsrc = xhalf ? W1r : W1l;
            int kb = k0 & 127;
            #pragma unroll
            for (int it = 0; it < 8; it++) {
                int f = tid + it * 256;
                int k = f >> 6;              // 0..31
                int n = (f & 63) * 4;        // 0..252
                float4 v = *(const float4*)&Wsrc[(size_t)(kb + k) * 256 + n];
                Ws[k][n + 0] = f2tf32(v.x); Ws[k][n + 1] = f2tf32(v.y);
                Ws[k][n + 2] = f2tf32(v.z); Ws[k][n + 3] = f2tf32(v.w);
            }
        }
        __syncthreads();

        #pragma unroll
        for (int k8 = 0; k8 < 32; k8 += 8) {
            unsigned a[4][4], b[8][2];
            #pragma unroll
            for (int mf = 0; mf < 4; mf++) {
                int mrow = warp_m * 64 + mf * 16 + qr;
                if (xhalf) {
                    a[mf][0] = As[mrow][k8 + qk];
                    a[mf][1] = As[mrow + 8][k8 + qk];
                    a[mf][2] = As[mrow][k8 + qk + 4];
                    a[mf][3] = As[mrow + 8][k8 + qk + 4];
                } else {
                    int kc = k0 + k8 + qk;
                    a[mf][0] = agg_s[mrow][kc];
                    a[mf][1] = agg_s[mrow + 8][kc];
                    a[mf][2] = agg_s[mrow][kc + 4];
                    a[mf][3] = agg_s[mrow + 8][kc + 4];
                }
            }
            #pragma unroll
            for (int nf = 0; nf < 8; nf++) {
                int ncol = warp_n * 64 + nf * 8 + qr;
                b[nf][0] = Ws[k8 + qk][ncol];
                b[nf][1] = Ws[k8 + qk + 4][ncol];
            }
            #pragma unroll
            for (int mf = 0; mf < 4; mf++)
                #pragma unroll
                for (int nf = 0; nf < 8; nf++) {
                    asm volatile(
                        "mma.sync.aligned.m16n8k8.row.col.f32.tf32.tf32.f32 "
                        "{%0,%1,%2,%3}, {%4,%5,%6,%7}, {%8,%9}, {%0,%1,%2,%3};"
                        : "+f"(d[mf][nf][0]), "+f"(d[mf][nf][1]),
                          "+f"(d[mf][nf][2]), "+f"(d[mf][nf][3])
                        : "r"(a[mf][0]), "r"(a[mf][1]), "r"(a[mf][2]), "r"(a[mf][3]),
                          "r"(b[nf][0]), "r"(b[nf][1]));
                }
        }
        __syncthreads();
    }

    // ---- epilogue: bias + relu -> g_h ----
    #pragma unroll
    for (int nf = 0; nf < 8; nf++) {
        int col = warp_n * 64 + nf * 8 + qk * 2;
        float2 bv = *(const float2*)&bias[col];
        #pragma unroll
        for (int mf = 0; mf < 4; mf++) {
            int r0 = row0 + warp_m * 64 + mf * 16 + qr;
            if (r0 < M) {
                float2 o = make_float2(fmaxf(d[mf][nf][0] + bv.x, 0.f),
                                       fmaxf(d[mf][nf][1] + bv.y, 0.f));
                *(float2*)&g_h[(size_t)r0 * 256 + col] = o;
            }
            if (r0 + 8 < M) {
                float2 o = make_float2(fmaxf(d[mf][nf][2] + bv.x, 0.f),
                                       fmaxf(d[mf][nf][3] + bv.y, 0.f));
                *(float2*)&g_h[(size_t)(r0 + 8) * 256 + col] = o;
            }
        }
    }
}

// ---------------- layer-2 GEMM: g_tu = g_h @ [W2l | W2r] ----------------
// Tile 128x128, BK=32, 256 threads = 8 warps (2m x 4n), warp tile 64x32.
__global__ void __launch_bounds__(256, 2)
gemm_tc1(const float* __restrict__ Wa, const float* __restrict__ Wb, int M) {
    __shared__ unsigned As[128][36];
    __shared__ unsigned Ws[32][136];

    int tid = threadIdx.x;
    int lane = tid & 31;
    int wid = tid >> 5;
    int warp_m = wid & 1;
    int warp_n = wid >> 1;
    int qk = lane & 3;
    int qr = lane >> 2;
    int row0 = blockIdx.y * 128;

    float d[4][4][4];
    #pragma unroll
    for (int i = 0; i < 4; i++)
        #pragma unroll
        for (int j = 0; j < 4; j++)
            #pragma unroll
            for (int q = 0; q < 4; q++) d[i][j][q] = 0.f;

    for (int k0 = 0; k0 < 256; k0 += 32) {
        #pragma unroll
        for (int it = 0; it < 4; it++) {
            int f = tid + it * 256;
            int m = f >> 3;
            int k = (f & 7) * 4;
            int grow = row0 + m;
            float4 v = make_float4(0, 0, 0, 0);
            if (grow < M) v = *(const float4*)&g_h[(size_t)grow * 256 + k0 + k];
            As[m][k + 0] = f2tf32(v.x); As[m][k + 1] = f2tf32(v.y);
            As[m][k + 2] = f2tf32(v.z); As[m][k + 3] = f2tf32(v.w);
        }
        #pragma unroll
        for (int it = 0; it < 4; it++) {
            int f = tid + it * 256;
            int k = f >> 5;
            int n = (f & 31) * 4;
            int kg = k0 + k;
            float4 v = (n < 64) ? *(const float4*)&Wa[(size_t)kg * 64 + n]
                                : *(const float4*)&Wb[(size_t)kg * 64 + (n - 64)];
            Ws[k][n + 0] = f2tf32(v.x); Ws[k][n + 1] = f2tf32(v.y);
            Ws[k][n + 2] = f2tf32(v.z); Ws[k][n + 3] = f2tf32(v.w);
        }
        __syncthreads();

        #pragma unroll
        for (int k8 = 0; k8 < 32; k8 += 8) {
            unsigned a[4][4], b[4][2];
            #pragma unroll
            for (int mf = 0; mf < 4; mf++) {
                int mrow = warp_m * 64 + mf * 16 + qr;
                a[mf][0] = As[mrow][k8 + qk];
                a[mf][1] = As[mrow + 8][k8 + qk];
                a[mf][2] = As[mrow][k8 + qk + 4];
                a[mf][3] = As[mrow + 8][k8 + qk + 4];
            }
            #pragma unroll
            for (int nf = 0; nf < 4; nf++) {
                int ncol = warp_n * 32 + nf * 8 + qr;
                b[nf][0] = Ws[k8 + qk][ncol];
                b[nf][1] = Ws[k8 + qk + 4][ncol];
            }
            #pragma unroll
            for (int mf = 0; mf < 4; mf++)
                #pragma unroll
                for (int nf = 0; nf < 4; nf++) {
                    asm volatile(
                        "mma.sync.aligned.m16n8k8.row.col.f32.tf32.tf32.f32 "
                        "{%0,%1,%2,%3}, {%4,%5,%6,%7}, {%8,%9}, {%0,%1,%2,%3};"
                        : "+f"(d[mf][nf][0]), "+f"(d[mf][nf][1]),
                          "+f"(d[mf][nf][2]), "+f"(d[mf][nf][3])
                        : "r"(a[mf][0]), "r"(a[mf][1]), "r"(a[mf][2]), "r"(a[mf][3]),
                          "r"(b[nf][0]), "r"(b[nf][1]));
                }
        }
        __syncthreads();
    }

    #pragma unroll
    for (int nf = 0; nf < 4; nf++) {
        int col = warp_n * 32 + nf * 8 + qk * 2;
        #pragma unroll
        for (int mf = 0; mf < 4; mf++) {
            int r0 = row0 + warp_m * 64 + mf * 16 + qr;
            if (r0 < M) {
                float2 o = make_float2(d[mf][nf][0], d[mf][nf][1]);
                *(float2*)&g_tu[(size_t)r0 * 128 + col] = o;
            }
            if (r0 + 8 < M) {
                float2 o = make_float2(d[mf][nf][2], d[mf][nf][3]);
                *(float2*)&g_tu[(size_t)(r0 + 8) * 128 + col] = o;
            }
        }
    }
}

// ---------------- final: out = sigmoid( mean_agg(t) + u + b2 ) ----------------
__global__ void agg_sig_kernel(const float* __restrict__ b2, float* __restrict__ out, int N) {
    int lane = threadIdx.x & 15;
    int node = blockIdx.x * 8 + (threadIdx.x >> 4);
    if (node >= N) return;
    int beg = g_off[node], end = g_off[node + 1];
    float4 acc = make_float4(0.f, 0.f, 0.f, 0.f);
    int e = beg;
    for (; e + 2 <= end; e += 2) {
        int s0 = g_bucket[e], s1 = g_bucket[e + 1];
        float4 v0 = *(const float4*)&g_tu[(size_t)s0 * 128 + lane * 4];
        float4 v1 = *(const float4*)&g_tu[(size_t)s1 * 128 + lane * 4];
        acc.x += v0.x + v1.x; acc.y += v0.y + v1.y;
        acc.z += v0.z + v1.z; acc.w += v0.w + v1.w;
    }
    for (; e < end; ++e) {
        int s = g_bucket[e];
        float4 v = *(const float4*)&g_tu[(size_t)s * 128 + lane * 4];
        acc.x += v.x; acc.y += v.y; acc.z += v.z; acc.w += v.w;
    }
    float inv = (end > beg) ? 1.f / (float)(end - beg) : 0.f;
    float4 u = *(const float4*)&g_tu[(size_t)node * 128 + 64 + lane * 4];
    float4 bv = *(const float4*)&b2[lane * 4];
    float4 o;
    o.x = 1.f / (1.f + __expf(-(acc.x * inv + u.x + bv.x)));
    o.y = 1.f / (1.f + __expf(-(acc.y * inv + u.y + bv.y)));
    o.z = 1.f / (1.f + __expf(-(acc.z * inv + u.z + bv.z)));
    o.w = 1.f / (1.f + __expf(-(acc.w * inv + u.w + bv.w)));
    *(float4*)&out[(size_t)node * 64 + lane * 4] = o;
}

// ---------------- launch ----------------
extern "C" void kernel_launch(void* const* d_in, const int* in_sizes, int n_in,
                              void* d_out, int out_size) {
    const float* x   = (const float*)d_in[0];
    const void*  ei  = d_in[1];
    const float* W1l = (const float*)d_in[2];
    const float* W1r = (const float*)d_in[3];
    const float* b1  = (const float*)d_in[4];
    const float* W2l = (const float*)d_in[5];
    const float* W2r = (const float*)d_in[6];
    const float* b2  = (const float*)d_in[7];
    float* out = (float*)d_out;

    int N = in_sizes[0] / 128;
    int E = in_sizes[1] / 2;
    int B = (N + 1023) / 1024;

    static bool attr_done = false;
    if (!attr_done) {
        cudaFuncSetAttribute(fused_l1, cudaFuncAttributeMaxDynamicSharedMemorySize,
                             L1_SMEM_WORDS * 4);
        attr_done = true;
    }

    detect_kernel<<<1, 64>>>((const int*)ei);
    zero_deg_kernel<<<(N + 255) / 256, 256>>>(N);
    count_kernel<<<(E + 255) / 256, 256>>>(ei, E, N);
    scan_blocks<<<B, 1024>>>(N);
    scan_bsums<<<1, 32>>>(B);
    finalize_off<<<(N + 255) / 256, 256>>>(N, E);
    fill_kernel<<<(E + 255) / 256, 256>>>(ei, E, N);

    {
        dim3 grid(1, (N + 127) / 128);
        fused_l1<<<grid, 256, L1_SMEM_WORDS * 4>>>(x, W1l, W1r, b1, N);
    }
    {
        dim3 grid(1, (N + 127) / 128);
        gemm_tc1<<<grid, 256>>>(W2l, W2r, N);
    }
    agg_sig_kernel<<<(N + 7) / 8, 128>>>(b2, out, N);
}

// round 7
// speedup vs baseline: 1.5826x; 1.5826x over previous
#include <cuda_runtime.h>
#include <cuda_bf16.h>
#include <cuda_fp16.h>
#include <cstdint>

#define MAXN 100000
#define MAXE 1600000

// ---------------- device scratch ----------------
__device__ int      g_is64;
__device__ int      g_deg[MAXN];
__device__ int      g_off[MAXN + 1];
__device__ int      g_cur[MAXN];
__device__ int      g_bsum[128];
__device__ int      g_bucket[MAXE];
__device__ __half   g_x16[(size_t)MAXN * 128];   // fp16 copy of x (gather source)
__device__ unsigned g_agg[(size_t)MAXN * 128];   // layer1 agg, pre-converted tf32 words
__device__ float    g_h[(size_t)MAXN * 256];     // hidden activations
__device__ __half   g_t16[(size_t)MAXN * 64];    // layer2 t = h@W2l (fp16, gets aggregated)
__device__ float    g_u[(size_t)MAXN * 64];      // layer2 u = h@W2r (fp32)

// ---------------- edge dtype detection ----------------
__global__ void detect_kernel(const int* __restrict__ w) {
    __shared__ int any;
    if (threadIdx.x == 0) any = 0;
    __syncthreads();
    if (w[2 * threadIdx.x + 1] != 0) atomicOr(&any, 1);
    __syncthreads();
    if (threadIdx.x == 0) g_is64 = (any == 0) ? 1 : 0;
}

__device__ __forceinline__ int load_idx(const void* ei, int pos) {
    if (g_is64) return (int)((const long long*)ei)[pos];
    return ((const int*)ei)[pos];
}

// ---------------- x -> fp16 copy, fused with g_deg zeroing ----------------
__global__ void convert_x_kernel(const float* __restrict__ x, int N) {
    int i = blockIdx.x * blockDim.x + threadIdx.x;
    int total4 = N * 32;  // N*128/4
    if (i < total4) {
        float4 v = ((const float4*)x)[i];
        __half2 a = __floats2half2_rn(v.x, v.y);
        __half2 b = __floats2half2_rn(v.z, v.w);
        uint2 o;
        o.x = *reinterpret_cast<unsigned*>(&a);
        o.y = *reinterpret_cast<unsigned*>(&b);
        *(uint2*)&g_x16[(size_t)i * 4] = o;
    }
    if (i < N) g_deg[i] = 0;
}

// ---------------- CSR construction ----------------
__global__ void count_kernel(const void* __restrict__ ei, int E, int N) {
    int e = blockIdx.x * blockDim.x + threadIdx.x;
    if (e < E) {
        int d = load_idx(ei, E + e);
        if ((unsigned)d < (unsigned)N) atomicAdd(&g_deg[d], 1);
    }
}

__global__ void scan_blocks(int N) {
    __shared__ int wsum[32];
    int i = blockIdx.x * 1024 + threadIdx.x;
    int lane = threadIdx.x & 31, wid = threadIdx.x >> 5;
    int v = (i < N) ? g_deg[i] : 0;
    int s = v;
    #pragma unroll
    for (int o = 1; o < 32; o <<= 1) {
        int t = __shfl_up_sync(0xffffffffu, s, o);
        if (lane >= o) s += t;
    }
    if (lane == 31) wsum[wid] = s;
    __syncthreads();
    if (wid == 0) {
        int ws = wsum[lane];
        #pragma unroll
        for (int o = 1; o < 32; o <<= 1) {
            int t = __shfl_up_sync(0xffffffffu, ws, o);
            if (lane >= o) ws += t;
        }
        wsum[lane] = ws;
    }
    __syncthreads();
    int incl = s + (wid > 0 ? wsum[wid - 1] : 0);
    if (i < N) g_off[i] = incl - v;
    if (threadIdx.x == 1023) g_bsum[blockIdx.x] = incl;
}

__global__ void scan_bsums(int B) {
    int lane = threadIdx.x;
    int carry = 0;
    for (int base = 0; base < B; base += 32) {
        int i = base + lane;
        int v = (i < B) ? g_bsum[i] : 0;
        int s = v;
        #pragma unroll
        for (int o = 1; o < 32; o <<= 1) {
            int t = __shfl_up_sync(0xffffffffu, s, o);
            if (lane >= o) s += t;
        }
        if (i < B) g_bsum[i] = carry + s - v;
        carry += __shfl_sync(0xffffffffu, s, 31);
    }
}

__global__ void finalize_off(int N, int E) {
    int i = blockIdx.x * blockDim.x + threadIdx.x;
    if (i < N) {
        int o = g_off[i] + g_bsum[i >> 10];
        g_off[i] = o;
        g_cur[i] = o;
    }
    if (i == 0) g_off[N] = E;
}

__global__ void fill_kernel(const void* __restrict__ ei, int E, int N) {
    int e = blockIdx.x * blockDim.x + threadIdx.x;
    if (e < E) {
        int s = load_idx(ei, e);
        int d = load_idx(ei, E + e);
        if ((unsigned)d < (unsigned)N && (unsigned)s < (unsigned)N) {
            int pos = atomicAdd(&g_cur[d], 1);
            g_bucket[pos] = s;
        }
    }
}

__device__ __forceinline__ unsigned f2tf32(float v) {
    unsigned r;
    asm("cvt.rna.tf32.f32 %0, %1;" : "=r"(r) : "f"(v));
    return r;
}

__device__ __forceinline__ void acc_h4(float4& acc, uint2 w) {
    __half2 h0 = *reinterpret_cast<__half2*>(&w.x);
    __half2 h1 = *reinterpret_cast<__half2*>(&w.y);
    float2 f0 = __half22float2(h0);
    float2 f1 = __half22float2(h1);
    acc.x += f0.x; acc.y += f0.y; acc.z += f1.x; acc.w += f1.y;
}

// ---------------- layer-1 mean aggregation (C=128, fp16 gather), warp per node ----------------
__global__ void agg128_kernel(int N) {
    int lane = threadIdx.x & 31;
    int node = blockIdx.x * 4 + (threadIdx.x >> 5);
    if (node >= N) return;
    int beg = g_off[node], end = g_off[node + 1];
    float4 acc = make_float4(0.f, 0.f, 0.f, 0.f);
    int e = beg;
    for (; e + 4 <= end; e += 4) {
        int s0 = g_bucket[e], s1 = g_bucket[e + 1], s2 = g_bucket[e + 2], s3 = g_bucket[e + 3];
        uint2 w0 = *(const uint2*)&g_x16[(size_t)s0 * 128 + lane * 4];
        uint2 w1 = *(const uint2*)&g_x16[(size_t)s1 * 128 + lane * 4];
        uint2 w2 = *(const uint2*)&g_x16[(size_t)s2 * 128 + lane * 4];
        uint2 w3 = *(const uint2*)&g_x16[(size_t)s3 * 128 + lane * 4];
        acc_h4(acc, w0); acc_h4(acc, w1); acc_h4(acc, w2); acc_h4(acc, w3);
    }
    for (; e < end; ++e) {
        int s = g_bucket[e];
        uint2 w = *(const uint2*)&g_x16[(size_t)s * 128 + lane * 4];
        acc_h4(acc, w);
    }
    float inv = (end > beg) ? 1.f / (float)(end - beg) : 0.f;
    uint4 t;
    t.x = f2tf32(acc.x * inv); t.y = f2tf32(acc.y * inv);
    t.z = f2tf32(acc.z * inv); t.w = f2tf32(acc.w * inv);
    *(uint4*)&g_agg[(size_t)node * 128 + lane * 4] = t;
}

// ---------------- layer-1 GEMM: g_h = relu([g_agg|x] @ [W1l;W1r] + b1) ----------------
// Tile 128x128, BK=32, 256 threads = 8 warps (2m x 4n), warp tile 64x32.
__global__ void __launch_bounds__(256, 2)
gemm_tc0(const float* __restrict__ x,
         const float* __restrict__ Wa, const float* __restrict__ Wb,
         const float* __restrict__ bias, int M) {
    __shared__ unsigned As[128][36];
    __shared__ unsigned Ws[32][136];

    int tid = threadIdx.x;
    int lane = tid & 31;
    int wid = tid >> 5;
    int warp_m = wid & 1;
    int warp_n = wid >> 1;
    int qk = lane & 3;
    int qr = lane >> 2;
    int row0 = blockIdx.y * 128;
    int col0 = blockIdx.x * 128;

    float d[4][4][4];
    #pragma unroll
    for (int i = 0; i < 4; i++)
        #pragma unroll
        for (int j = 0; j < 4; j++)
            #pragma unroll
            for (int q = 0; q < 4; q++) d[i][j][q] = 0.f;

    for (int k0 = 0; k0 < 256; k0 += 32) {
        bool xhalf = (k0 >= 128);
        #pragma unroll
        for (int it = 0; it < 4; it++) {
            int f = tid + it * 256;
            int m = f >> 3;
            int k = (f & 7) * 4;
            int grow = row0 + m;
            if (xhalf) {
                float4 v = make_float4(0, 0, 0, 0);
                if (grow < M) v = *(const float4*)&x[(size_t)grow * 128 + (k0 - 128) + k];
                As[m][k + 0] = f2tf32(v.x); As[m][k + 1] = f2tf32(v.y);
                As[m][k + 2] = f2tf32(v.z); As[m][k + 3] = f2tf32(v.w);
            } else {
                uint4 v = make_uint4(0, 0, 0, 0);
                if (grow < M) v = *(const uint4*)&g_agg[(size_t)grow * 128 + k0 + k];
                As[m][k + 0] = v.x; As[m][k + 1] = v.y;
                As[m][k + 2] = v.z; As[m][k + 3] = v.w;
            }
        }
        {
            const float* Wsrc = xhalf ? Wb : Wa;
            int kb = k0 & 127;
            #pragma unroll
            for (int it = 0; it < 4; it++) {
                int f = tid + it * 256;
                int k = f >> 5;
                int n = (f & 31) * 4;
                float4 v = *(const float4*)&Wsrc[(size_t)(kb + k) * 256 + col0 + n];
                Ws[k][n + 0] = f2tf32(v.x); Ws[k][n + 1] = f2tf32(v.y);
                Ws[k][n + 2] = f2tf32(v.z); Ws[k][n + 3] = f2tf32(v.w);
            }
        }
        __syncthreads();

        #pragma unroll
        for (int k8 = 0; k8 < 32; k8 += 8) {
            unsigned a[4][4], b[4][2];
            #pragma unroll
            for (int mf = 0; mf < 4; mf++) {
                int mrow = warp_m * 64 + mf * 16 + qr;
                a[mf][0] = As[mrow][k8 + qk];
                a[mf][1] = As[mrow + 8][k8 + qk];
                a[mf][2] = As[mrow][k8 + qk + 4];
                a[mf][3] = As[mrow + 8][k8 + qk + 4];
            }
            #pragma unroll
            for (int nf = 0; nf < 4; nf++) {
                int ncol = warp_n * 32 + nf * 8 + qr;
                b[nf][0] = Ws[k8 + qk][ncol];
                b[nf][1] = Ws[k8 + qk + 4][ncol];
            }
            #pragma unroll
            for (int mf = 0; mf < 4; mf++)
                #pragma unroll
                for (int nf = 0; nf < 4; nf++) {
                    asm volatile(
                        "mma.sync.aligned.m16n8k8.row.col.f32.tf32.tf32.f32 "
                        "{%0,%1,%2,%3}, {%4,%5,%6,%7}, {%8,%9}, {%0,%1,%2,%3};"
                        : "+f"(d[mf][nf][0]), "+f"(d[mf][nf][1]),
                          "+f"(d[mf][nf][2]), "+f"(d[mf][nf][3])
                        : "r"(a[mf][0]), "r"(a[mf][1]), "r"(a[mf][2]), "r"(a[mf][3]),
                          "r"(b[nf][0]), "r"(b[nf][1]));
                }
        }
        __syncthreads();
    }

    #pragma unroll
    for (int nf = 0; nf < 4; nf++) {
        int col = col0 + warp_n * 32 + nf * 8 + qk * 2;
        float2 bv = *(const float2*)&bias[col];
        #pragma unroll
        for (int mf = 0; mf < 4; mf++) {
            int r0 = row0 + warp_m * 64 + mf * 16 + qr;
            if (r0 < M) {
                float2 o = make_float2(fmaxf(d[mf][nf][0] + bv.x, 0.f),
                                       fmaxf(d[mf][nf][1] + bv.y, 0.f));
                *(float2*)&g_h[(size_t)r0 * 256 + col] = o;
            }
            if (r0 + 8 < M) {
                float2 o = make_float2(fmaxf(d[mf][nf][2] + bv.x, 0.f),
                                       fmaxf(d[mf][nf][3] + bv.y, 0.f));
                *(float2*)&g_h[(size_t)(r0 + 8) * 256 + col] = o;
            }
        }
    }
}

// ---------------- layer-2 GEMM: t16 = h@W2l (fp16), u = h@W2r (fp32) ----------------
__global__ void __launch_bounds__(256, 2)
gemm_tc1(const float* __restrict__ Wa, const float* __restrict__ Wb, int M) {
    __shared__ unsigned As[128][36];
    __shared__ unsigned Ws[32][136];

    int tid = threadIdx.x;
    int lane = tid & 31;
    int wid = tid >> 5;
    int warp_m = wid & 1;
    int warp_n = wid >> 1;
    int qk = lane & 3;
    int qr = lane >> 2;
    int row0 = blockIdx.y * 128;

    float d[4][4][4];
    #pragma unroll
    for (int i = 0; i < 4; i++)
        #pragma unroll
        for (int j = 0; j < 4; j++)
            #pragma unroll
            for (int q = 0; q < 4; q++) d[i][j][q] = 0.f;

    for (int k0 = 0; k0 < 256; k0 += 32) {
        #pragma unroll
        for (int it = 0; it < 4; it++) {
            int f = tid + it * 256;
            int m = f >> 3;
            int k = (f & 7) * 4;
            int grow = row0 + m;
            float4 v = make_float4(0, 0, 0, 0);
            if (grow < M) v = *(const float4*)&g_h[(size_t)grow * 256 + k0 + k];
            As[m][k + 0] = f2tf32(v.x); As[m][k + 1] = f2tf32(v.y);
            As[m][k + 2] = f2tf32(v.z); As[m][k + 3] = f2tf32(v.w);
        }
        #pragma unroll
        for (int it = 0; it < 4; it++) {
            int f = tid + it * 256;
            int k = f >> 5;
            int n = (f & 31) * 4;
            int kg = k0 + k;
            float4 v = (n < 64) ? *(const float4*)&Wa[(size_t)kg * 64 + n]
                                : *(const float4*)&Wb[(size_t)kg * 64 + (n - 64)];
            Ws[k][n + 0] = f2tf32(v.x); Ws[k][n + 1] = f2tf32(v.y);
            Ws[k][n + 2] = f2tf32(v.z); Ws[k][n + 3] = f2tf32(v.w);
        }
        __syncthreads();

        #pragma unroll
        for (int k8 = 0; k8 < 32; k8 += 8) {
            unsigned a[4][4], b[4][2];
            #pragma unroll
            for (int mf = 0; mf < 4; mf++) {
                int mrow = warp_m * 64 + mf * 16 + qr;
                a[mf][0] = As[mrow][k8 + qk];
                a[mf][1] = As[mrow + 8][k8 + qk];
                a[mf][2] = As[mrow][k8 + qk + 4];
                a[mf][3] = As[mrow + 8][k8 + qk + 4];
            }
            #pragma unroll
            for (int nf = 0; nf < 4; nf++) {
                int ncol = warp_n * 32 + nf * 8 + qr;
                b[nf][0] = Ws[k8 + qk][ncol];
                b[nf][1] = Ws[k8 + qk + 4][ncol];
            }
            #pragma unroll
            for (int mf = 0; mf < 4; mf++)
                #pragma unroll
                for (int nf = 0; nf < 4; nf++) {
                    asm volatile(
                        "mma.sync.aligned.m16n8k8.row.col.f32.tf32.tf32.f32 "
                        "{%0,%1,%2,%3}, {%4,%5,%6,%7}, {%8,%9}, {%0,%1,%2,%3};"
                        : "+f"(d[mf][nf][0]), "+f"(d[mf][nf][1]),
                          "+f"(d[mf][nf][2]), "+f"(d[mf][nf][3])
                        : "r"(a[mf][0]), "r"(a[mf][1]), "r"(a[mf][2]), "r"(a[mf][3]),
                          "r"(b[nf][0]), "r"(b[nf][1]));
                }
        }
        __syncthreads();
    }

    // epilogue: cols [0,64) -> t as fp16; cols [64,128) -> u as fp32
    #pragma unroll
    for (int nf = 0; nf < 4; nf++) {
        int col = warp_n * 32 + nf * 8 + qk * 2;   // 0..127
        #pragma unroll
        for (int mf = 0; mf < 4; mf++) {
            int r0 = row0 + warp_m * 64 + mf * 16 + qr;
            if (col < 64) {
                if (r0 < M) {
                    __half2 hh = __floats2half2_rn(d[mf][nf][0], d[mf][nf][1]);
                    *(__half2*)&g_t16[(size_t)r0 * 64 + col] = hh;
                }
                if (r0 + 8 < M) {
                    __half2 hh = __floats2half2_rn(d[mf][nf][2], d[mf][nf][3]);
                    *(__half2*)&g_t16[(size_t)(r0 + 8) * 64 + col] = hh;
                }
            } else {
                if (r0 < M) {
                    float2 o = make_float2(d[mf][nf][0], d[mf][nf][1]);
                    *(float2*)&g_u[(size_t)r0 * 64 + (col - 64)] = o;
                }
                if (r0 + 8 < M) {
                    float2 o = make_float2(d[mf][nf][2], d[mf][nf][3]);
                    *(float2*)&g_u[(size_t)(r0 + 8) * 64 + (col - 64)] = o;
                }
            }
        }
    }
}

// ---------------- final: out = sigmoid( mean_agg(t16) + u + b2 ) ----------------
__global__ void agg_sig_kernel(const float* __restrict__ b2, float* __restrict__ out, int N) {
    int lane = threadIdx.x & 15;
    int node = blockIdx.x * 8 + (threadIdx.x >> 4);
    if (node >= N) return;
    int beg = g_off[node], end = g_off[node + 1];
    float4 acc = make_float4(0.f, 0.f, 0.f, 0.f);
    int e = beg;
    for (; e + 4 <= end; e += 4) {
        int s0 = g_bucket[e], s1 = g_bucket[e + 1], s2 = g_bucket[e + 2], s3 = g_bucket[e + 3];
        uint2 w0 = *(const uint2*)&g_t16[(size_t)s0 * 64 + lane * 4];
        uint2 w1 = *(const uint2*)&g_t16[(size_t)s1 * 64 + lane * 4];
        uint2 w2 = *(const uint2*)&g_t16[(size_t)s2 * 64 + lane * 4];
        uint2 w3 = *(const uint2*)&g_t16[(size_t)s3 * 64 + lane * 4];
        acc_h4(acc, w0); acc_h4(acc, w1); acc_h4(acc, w2); acc_h4(acc, w3);
    }
    for (; e < end; ++e) {
        int s = g_bucket[e];
        uint2 w = *(const uint2*)&g_t16[(size_t)s * 64 + lane * 4];
        acc_h4(acc, w);
    }
    float inv = (end > beg) ? 1.f / (float)(end - beg) : 0.f;
    float4 u = *(const float4*)&g_u[(size_t)node * 64 + lane * 4];
    float4 bv = *(const float4*)&b2[lane * 4];
    float4 o;
    o.x = 1.f / (1.f + __expf(-(acc.x * inv + u.x + bv.x)));
    o.y = 1.f / (1.f + __expf(-(acc.y * inv + u.y + bv.y)));
    o.z = 1.f / (1.f + __expf(-(acc.z * inv + u.z + bv.z)));
    o.w = 1.f / (1.f + __expf(-(acc.w * inv + u.w + bv.w)));
    *(float4*)&out[(size_t)node * 64 + lane * 4] = o;
}

// ---------------- launch ----------------
extern "C" void kernel_launch(void* const* d_in, const int* in_sizes, int n_in,
                              void* d_out, int out_size) {
    const float* x   = (const float*)d_in[0];
    const void*  ei  = d_in[1];
    const float* W1l = (const float*)d_in[2];
    const float* W1r = (const float*)d_in[3];
    const float* b1  = (const float*)d_in[4];
    const float* W2l = (const float*)d_in[5];
    const float* W2r = (const float*)d_in[6];
    const float* b2  = (const float*)d_in[7];
    float* out = (float*)d_out;

    int N = in_sizes[0] / 128;
    int E = in_sizes[1] / 2;
    int B = (N + 1023) / 1024;

    detect_kernel<<<1, 64>>>((const int*)ei);
    convert_x_kernel<<<(N * 32 + 255) / 256, 256>>>(x, N);   // also zeroes g_deg
    count_kernel<<<(E + 255) / 256, 256>>>(ei, E, N);
    scan_blocks<<<B, 1024>>>(N);
    scan_bsums<<<1, 32>>>(B);
    finalize_off<<<(N + 255) / 256, 256>>>(N, E);
    fill_kernel<<<(E + 255) / 256, 256>>>(ei, E, N);

    agg128_kernel<<<(N + 3) / 4, 128>>>(N);
    {
        dim3 grid(2, (N + 127) / 128);
        gemm_tc0<<<grid, 256>>>(x, W1l, W1r, b1, N);
    }
    {
        dim3 grid(1, (N + 127) / 128);
        gemm_tc1<<<grid, 256>>>(W2l, W2r, N);
    }
    agg_sig_kernel<<<(N + 7) / 8, 128>>>(b2, out, N);
}

// round 8
// speedup vs baseline: 2.1021x; 1.3283x over previous
#include <cuda_runtime.h>
#include <cuda_bf16.h>
#include <cuda_fp16.h>
#include <cstdint>

#define MAXN 100000
#define MAXE 1600000

// ---------------- device scratch ----------------
__device__ int      g_is64;
__device__ int      g_deg[MAXN];
__device__ int      g_off[MAXN + 1];
__device__ int      g_cur[MAXN];
__device__ int      g_bsum[128];
__device__ int      g_bucket[MAXE];
__device__ __half   g_x16[(size_t)MAXN * 128];   // fp16 copy of x
__device__ __half   g_agg16[(size_t)MAXN * 128]; // layer1 agg (fp16)
__device__ __half   g_h16[(size_t)MAXN * 256];   // hidden activations (fp16)
__device__ __half   g_t16[(size_t)MAXN * 64];    // layer2 t = h@W2l (fp16, aggregated)
__device__ float    g_u[(size_t)MAXN * 64];      // layer2 u = h@W2r (fp32)

// ---------------- edge dtype detection ----------------
__global__ void detect_kernel(const int* __restrict__ w) {
    __shared__ int any;
    if (threadIdx.x == 0) any = 0;
    __syncthreads();
    if (w[2 * threadIdx.x + 1] != 0) atomicOr(&any, 1);
    __syncthreads();
    if (threadIdx.x == 0) g_is64 = (any == 0) ? 1 : 0;
}

__device__ __forceinline__ int load_idx(const void* ei, int pos) {
    if (g_is64) return (int)((const long long*)ei)[pos];
    return ((const int*)ei)[pos];
}

// ---------------- x -> fp16 copy, fused with g_deg zeroing ----------------
__global__ void convert_x_kernel(const float* __restrict__ x, int N) {
    int i = blockIdx.x * blockDim.x + threadIdx.x;
    int total4 = N * 32;
    if (i < total4) {
        float4 v = ((const float4*)x)[i];
        __half2 a = __floats2half2_rn(v.x, v.y);
        __half2 b = __floats2half2_rn(v.z, v.w);
        uint2 o;
        o.x = *reinterpret_cast<unsigned*>(&a);
        o.y = *reinterpret_cast<unsigned*>(&b);
        *(uint2*)&g_x16[(size_t)i * 4] = o;
    }
    if (i < N) g_deg[i] = 0;
}

// ---------------- CSR construction ----------------
__global__ void count_kernel(const void* __restrict__ ei, int E, int N) {
    int e = blockIdx.x * blockDim.x + threadIdx.x;
    if (e < E) {
        int d = load_idx(ei, E + e);
        if ((unsigned)d < (unsigned)N) atomicAdd(&g_deg[d], 1);
    }
}

__global__ void scan_blocks(int N) {
    __shared__ int wsum[32];
    int i = blockIdx.x * 1024 + threadIdx.x;
    int lane = threadIdx.x & 31, wid = threadIdx.x >> 5;
    int v = (i < N) ? g_deg[i] : 0;
    int s = v;
    #pragma unroll
    for (int o = 1; o < 32; o <<= 1) {
        int t = __shfl_up_sync(0xffffffffu, s, o);
        if (lane >= o) s += t;
    }
    if (lane == 31) wsum[wid] = s;
    __syncthreads();
    if (wid == 0) {
        int ws = wsum[lane];
        #pragma unroll
        for (int o = 1; o < 32; o <<= 1) {
            int t = __shfl_up_sync(0xffffffffu, ws, o);
            if (lane >= o) ws += t;
        }
        wsum[lane] = ws;
    }
    __syncthreads();
    int incl = s + (wid > 0 ? wsum[wid - 1] : 0);
    if (i < N) g_off[i] = incl - v;
    if (threadIdx.x == 1023) g_bsum[blockIdx.x] = incl;
}

__global__ void scan_bsums(int B) {
    int lane = threadIdx.x;
    int carry = 0;
    for (int base = 0; base < B; base += 32) {
        int i = base + lane;
        int v = (i < B) ? g_bsum[i] : 0;
        int s = v;
        #pragma unroll
        for (int o = 1; o < 32; o <<= 1) {
            int t = __shfl_up_sync(0xffffffffu, s, o);
            if (lane >= o) s += t;
        }
        if (i < B) g_bsum[i] = carry + s - v;
        carry += __shfl_sync(0xffffffffu, s, 31);
    }
}

__global__ void finalize_off(int N, int E) {
    int i = blockIdx.x * blockDim.x + threadIdx.x;
    if (i < N) {
        int o = g_off[i] + g_bsum[i >> 10];
        g_off[i] = o;
        g_cur[i] = o;
    }
    if (i == 0) g_off[N] = E;
}

__global__ void fill_kernel(const void* __restrict__ ei, int E, int N) {
    int e = blockIdx.x * blockDim.x + threadIdx.x;
    if (e < E) {
        int s = load_idx(ei, e);
        int d = load_idx(ei, E + e);
        if ((unsigned)d < (unsigned)N && (unsigned)s < (unsigned)N) {
            int pos = atomicAdd(&g_cur[d], 1);
            g_bucket[pos] = s;
        }
    }
}

__device__ __forceinline__ void acc_h4(float4& acc, uint2 w) {
    __half2 h0 = *reinterpret_cast<__half2*>(&w.x);
    __half2 h1 = *reinterpret_cast<__half2*>(&w.y);
    float2 f0 = __half22float2(h0);
    float2 f1 = __half22float2(h1);
    acc.x += f0.x; acc.y += f0.y; acc.z += f1.x; acc.w += f1.y;
}

__device__ __forceinline__ unsigned packh2(float a, float b) {
    __half2 h = __floats2half2_rn(a, b);
    return *reinterpret_cast<unsigned*>(&h);
}

// ---------------- layer-1 mean aggregation (C=128, fp16 in/out), warp per node ----------------
__global__ void agg128_kernel(int N) {
    int lane = threadIdx.x & 31;
    int node = blockIdx.x * 4 + (threadIdx.x >> 5);
    if (node >= N) return;
    int beg = g_off[node], end = g_off[node + 1];
    float4 acc = make_float4(0.f, 0.f, 0.f, 0.f);
    int e = beg;
    for (; e + 4 <= end; e += 4) {
        int s0 = g_bucket[e], s1 = g_bucket[e + 1], s2 = g_bucket[e + 2], s3 = g_bucket[e + 3];
        uint2 w0 = *(const uint2*)&g_x16[(size_t)s0 * 128 + lane * 4];
        uint2 w1 = *(const uint2*)&g_x16[(size_t)s1 * 128 + lane * 4];
        uint2 w2 = *(const uint2*)&g_x16[(size_t)s2 * 128 + lane * 4];
        uint2 w3 = *(const uint2*)&g_x16[(size_t)s3 * 128 + lane * 4];
        acc_h4(acc, w0); acc_h4(acc, w1); acc_h4(acc, w2); acc_h4(acc, w3);
    }
    for (; e < end; ++e) {
        int s = g_bucket[e];
        uint2 w = *(const uint2*)&g_x16[(size_t)s * 128 + lane * 4];
        acc_h4(acc, w);
    }
    float inv = (end > beg) ? 1.f / (float)(end - beg) : 0.f;
    uint2 o;
    o.x = packh2(acc.x * inv, acc.y * inv);
    o.y = packh2(acc.z * inv, acc.w * inv);
    *(uint2*)&g_agg16[(size_t)node * 128 + lane * 4] = o;
}

// ---------------- fp16 MMA GEMMs (m16n8k16) ----------------
// Block tile 128x128, BK=32, 256 threads = 8 warps (2m x 4n), warp tile 64x32.
// As: half2 words [128][20] (16 k2 + 4 pad; stride%32==20 -> conflict-free 4g+t)
// Ws: half2 words [16][136]  (word [k2][n] = {B[2k2][n], B[2k2+1][n]}; stride%32==8)

#define MMA_H16(d, a, b)                                                        \
    asm volatile(                                                               \
        "mma.sync.aligned.m16n8k16.row.col.f32.f16.f16.f32 "                    \
        "{%0,%1,%2,%3}, {%4,%5,%6,%7}, {%8,%9}, {%0,%1,%2,%3};"                 \
        : "+f"(d[0]), "+f"(d[1]), "+f"(d[2]), "+f"(d[3])                        \
        : "r"(a[0]), "r"(a[1]), "r"(a[2]), "r"(a[3]), "r"(b[0]), "r"(b[1]))

// MODE 0: g_h16 = relu([g_agg16|g_x16](K=256) @ [W1l;W1r] + b1), NO=256 (grid.x=2)
// MODE 1: [t16|u] = g_h16 (K=256) @ [W2l|W2r] col-concat,        NO=128 (grid.x=1)
template <int MODE>
__global__ void __launch_bounds__(256, 2)
gemm_h16(const float* __restrict__ Wa, const float* __restrict__ Wb,
         const float* __restrict__ bias, int M) {
    __shared__ unsigned As[128][20];
    __shared__ unsigned Ws[16][136];

    int tid = threadIdx.x;
    int lane = tid & 31;
    int wid = tid >> 5;
    int warp_m = wid & 1;
    int warp_n = wid >> 1;
    int qk = lane & 3;       // t (thread-in-group)
    int qr = lane >> 2;      // g (group)
    int row0 = blockIdx.y * 128;
    int col0 = blockIdx.x * 128;

    float d[4][4][4];
    #pragma unroll
    for (int i = 0; i < 4; i++)
        #pragma unroll
        for (int j = 0; j < 4; j++)
            #pragma unroll
            for (int q = 0; q < 4; q++) d[i][j][q] = 0.f;

    for (int k0 = 0; k0 < 256; k0 += 32) {
        // ---- A tile: 128 rows x 32 halves; 2 uint4 per thread ----
        #pragma unroll
        for (int it = 0; it < 2; it++) {
            int f = tid + it * 256;      // 0..511
            int m = f >> 2;              // row 0..127
            int q = f & 3;               // 8-half group
            int grow = row0 + m;
            uint4 v = make_uint4(0, 0, 0, 0);
            if (grow < M) {
                if (MODE == 0) {
                    const __half* src = (k0 < 128) ? g_agg16 : g_x16;
                    v = *(const uint4*)&src[(size_t)grow * 128 + (k0 & 127) + q * 8];
                } else {
                    v = *(const uint4*)&g_h16[(size_t)grow * 256 + k0 + q * 8];
                }
            }
            *(uint4*)&As[m][q * 4] = v;
        }
        // ---- W tile: 32 k x 128 n, packed as k-pairs; 2 tasks per thread ----
        #pragma unroll
        for (int it = 0; it < 2; it++) {
            int task = tid + it * 256;   // 0..511
            int k2 = task >> 5;          // 0..15
            int n = (task & 31) * 4;     // 0..124
            float4 w0, w1;
            if (MODE == 0) {
                const float* Wsrc = (k0 < 128) ? Wa : Wb;
                int kr = (k0 & 127) + 2 * k2;
                w0 = *(const float4*)&Wsrc[(size_t)kr * 256 + col0 + n];
                w1 = *(const float4*)&Wsrc[(size_t)(kr + 1) * 256 + col0 + n];
            } else {
                int kg = k0 + 2 * k2;
                if (n < 64) {
                    w0 = *(const float4*)&Wa[(size_t)kg * 64 + n];
                    w1 = *(const float4*)&Wa[(size_t)(kg + 1) * 64 + n];
                } else {
                    w0 = *(const float4*)&Wb[(size_t)kg * 64 + (n - 64)];
                    w1 = *(const float4*)&Wb[(size_t)(kg + 1) * 64 + (n - 64)];
                }
            }
            uint4 o;
            o.x = packh2(w0.x, w1.x);
            o.y = packh2(w0.y, w1.y);
            o.z = packh2(w0.z, w1.z);
            o.w = packh2(w0.w, w1.w);
            *(uint4*)&Ws[k2][n] = o;
        }
        __syncthreads();

        // ---- 2 x m16n8k16 per BK=32 ----
        #pragma unroll
        for (int kk = 0; kk < 2; kk++) {
            int k2b = kk * 8;
            unsigned a[4][4], b[4][2];
            #pragma unroll
            for (int mf = 0; mf < 4; mf++) {
                int mrow = warp_m * 64 + mf * 16 + qr;
                a[mf][0] = As[mrow][k2b + qk];
                a[mf][1] = As[mrow + 8][k2b + qk];
                a[mf][2] = As[mrow][k2b + qk + 4];
                a[mf][3] = As[mrow + 8][k2b + qk + 4];
            }
            #pragma unroll
            for (int nf = 0; nf < 4; nf++) {
                int ncol = warp_n * 32 + nf * 8 + qr;
                b[nf][0] = Ws[k2b + qk][ncol];
                b[nf][1] = Ws[k2b + qk + 4][ncol];
            }
            #pragma unroll
            for (int mf = 0; mf < 4; mf++)
                #pragma unroll
                for (int nf = 0; nf < 4; nf++)
                    MMA_H16(d[mf][nf], a[mf], b[nf]);
        }
        __syncthreads();
    }

    // ---- epilogue ----
    #pragma unroll
    for (int nf = 0; nf < 4; nf++) {
        int col = col0 + warp_n * 32 + nf * 8 + qk * 2;
        if (MODE == 0) {
            float2 bv = *(const float2*)&bias[col];
            #pragma unroll
            for (int mf = 0; mf < 4; mf++) {
                int r0 = row0 + warp_m * 64 + mf * 16 + qr;
                if (r0 < M) {
                    unsigned hh = packh2(fmaxf(d[mf][nf][0] + bv.x, 0.f),
                                         fmaxf(d[mf][nf][1] + bv.y, 0.f));
                    *(unsigned*)&g_h16[(size_t)r0 * 256 + col] = hh;
                }
                if (r0 + 8 < M) {
                    unsigned hh = packh2(fmaxf(d[mf][nf][2] + bv.x, 0.f),
                                         fmaxf(d[mf][nf][3] + bv.y, 0.f));
                    *(unsigned*)&g_h16[(size_t)(r0 + 8) * 256 + col] = hh;
                }
            }
        } else {
            #pragma unroll
            for (int mf = 0; mf < 4; mf++) {
                int r0 = row0 + warp_m * 64 + mf * 16 + qr;
                if (col < 64) {
                    if (r0 < M) {
                        unsigned hh = packh2(d[mf][nf][0], d[mf][nf][1]);
                        *(unsigned*)&g_t16[(size_t)r0 * 64 + col] = hh;
                    }
                    if (r0 + 8 < M) {
                        unsigned hh = packh2(d[mf][nf][2], d[mf][nf][3]);
                        *(unsigned*)&g_t16[(size_t)(r0 + 8) * 64 + col] = hh;
                    }
                } else {
                    if (r0 < M) {
                        float2 o = make_float2(d[mf][nf][0], d[mf][nf][1]);
                        *(float2*)&g_u[(size_t)r0 * 64 + (col - 64)] = o;
                    }
                    if (r0 + 8 < M) {
                        float2 o = make_float2(d[mf][nf][2], d[mf][nf][3]);
                        *(float2*)&g_u[(size_t)(r0 + 8) * 64 + (col - 64)] = o;
                    }
                }
            }
        }
    }
}

// ---------------- final: out = sigmoid( mean_agg(t16) + u + b2 ) ----------------
__global__ void agg_sig_kernel(const float* __restrict__ b2, float* __restrict__ out, int N) {
    int lane = threadIdx.x & 15;
    int node = blockIdx.x * 8 + (threadIdx.x >> 4);
    if (node >= N) return;
    int beg = g_off[node], end = g_off[node + 1];
    float4 acc = make_float4(0.f, 0.f, 0.f, 0.f);
    int e = beg;
    for (; e + 4 <= end; e += 4) {
        int s0 = g_bucket[e], s1 = g_bucket[e + 1], s2 = g_bucket[e + 2], s3 = g_bucket[e + 3];
        uint2 w0 = *(const uint2*)&g_t16[(size_t)s0 * 64 + lane * 4];
        uint2 w1 = *(const uint2*)&g_t16[(size_t)s1 * 64 + lane * 4];
        uint2 w2 = *(const uint2*)&g_t16[(size_t)s2 * 64 + lane * 4];
        uint2 w3 = *(const uint2*)&g_t16[(size_t)s3 * 64 + lane * 4];
        acc_h4(acc, w0); acc_h4(acc, w1); acc_h4(acc, w2); acc_h4(acc, w3);
    }
    for (; e < end; ++e) {
        int s = g_bucket[e];
        uint2 w = *(const uint2*)&g_t16[(size_t)s * 64 + lane * 4];
        acc_h4(acc, w);
    }
    float inv = (end > beg) ? 1.f / (float)(end - beg) : 0.f;
    float4 u = *(const float4*)&g_u[(size_t)node * 64 + lane * 4];
    float4 bv = *(const float4*)&b2[lane * 4];
    float4 o;
    o.x = 1.f / (1.f + __expf(-(acc.x * inv + u.x + bv.x)));
    o.y = 1.f / (1.f + __expf(-(acc.y * inv + u.y + bv.y)));
    o.z = 1.f / (1.f + __expf(-(acc.z * inv + u.z + bv.z)));
    o.w = 1.f / (1.f + __expf(-(acc.w * inv + u.w + bv.w)));
    *(float4*)&out[(size_t)node * 64 + lane * 4] = o;
}

// ---------------- launch ----------------
extern "C" void kernel_launch(void* const* d_in, const int* in_sizes, int n_in,
                              void* d_out, int out_size) {
    const float* x   = (const float*)d_in[0];
    const void*  ei  = d_in[1];
    const float* W1l = (const float*)d_in[2];
    const float* W1r = (const float*)d_in[3];
    const float* b1  = (const float*)d_in[4];
    const float* W2l = (const float*)d_in[5];
    const float* W2r = (const float*)d_in[6];
    const float* b2  = (const float*)d_in[7];
    float* out = (float*)d_out;

    int N = in_sizes[0] / 128;
    int E = in_sizes[1] / 2;
    int B = (N + 1023) / 1024;

    detect_kernel<<<1, 64>>>((const int*)ei);
    convert_x_kernel<<<(N * 32 + 255) / 256, 256>>>(x, N);   // also zeroes g_deg
    count_kernel<<<(E + 255) / 256, 256>>>(ei, E, N);
    scan_blocks<<<B, 1024>>>(N);
    scan_bsums<<<1, 32>>>(B);
    finalize_off<<<(N + 255) / 256, 256>>>(N, E);
    fill_kernel<<<(E + 255) / 256, 256>>>(ei, E, N);

    agg128_kernel<<<(N + 3) / 4, 128>>>(N);
    {
        dim3 grid(2, (N + 127) / 128);
        gemm_h16<0><<<grid, 256>>>(W1l, W1r, b1, N);
    }
    {
        dim3 grid(1, (N + 127) / 128);
        gemm_h16<1><<<grid, 256>>>(W2l, W2r, nullptr, N);
    }
    agg_sig_kernel<<<(N + 7) / 8, 128>>>(b2, out, N);
}